// round 7
// baseline (speedup 1.0000x reference)
#include <cuda_runtime.h>
#include <cstdint>

#define V_NODES   1000000
#define N_GRAPHS  50000
#define NODE_DIM  128
#define HIDDEN    128
#define GDIM      64

// ---------------- scratch ----------------
__device__ __align__(256) float    g_Z1[(size_t)N_GRAPHS * HIDDEN];
__device__ __align__(256) int      g_cnti[N_GRAPHS];
__device__ __align__(256) int      g_pos[N_GRAPHS];     // scan result, consumed by scatter
__device__ __align__(256) int      g_sorted[V_NODES];   // node ids grouped by graph
__device__ __align__(256) int      g_sgid[V_NODES];     // graph id per sorted slot
__device__ __align__(256) unsigned g_Wtf[256 * NODE_DIM]; // W1/W2 interleaved, tf32 bits
__device__ int g_is64;

// ---------------- helpers ----------------
__device__ __forceinline__ unsigned f2tf(float f) {
    unsigned u;
    asm("cvt.rna.tf32.f32 %0, %1;" : "=r"(u) : "f"(f));
    return u;
}

__device__ __forceinline__ void mma_tf32(float& c0, float& c1, float& c2, float& c3,
                                         unsigned a0, unsigned a1, unsigned a2, unsigned a3,
                                         unsigned b0, unsigned b1) {
    asm volatile(
        "mma.sync.aligned.m16n8k8.row.col.f32.tf32.tf32.f32 "
        "{%0,%1,%2,%3},{%4,%5,%6,%7},{%8,%9},{%0,%1,%2,%3};"
        : "+f"(c0), "+f"(c1), "+f"(c2), "+f"(c3)
        : "r"(a0), "r"(a1), "r"(a2), "r"(a3), "r"(b0), "r"(b1));
}

__device__ __forceinline__ void red4(float* p, float4 v) {
    asm volatile("red.global.add.v4.f32 [%0], {%1,%2,%3,%4};"
                 :: "l"(p), "f"(v.x), "f"(v.y), "f"(v.z), "f"(v.w) : "memory");
}

__device__ __forceinline__ float sigm(float x) { return 1.0f / (1.0f + __expf(-x)); }

__device__ __forceinline__ unsigned s2u(const void* p) {
    return (unsigned)__cvta_generic_to_shared(p);
}

__device__ __forceinline__ void cp16(unsigned dst, const void* src, unsigned sz) {
    asm volatile("cp.async.cg.shared.global [%0], [%1], 16, %2;"
                 :: "r"(dst), "l"(src), "r"(sz));
}
__device__ __forceinline__ void cp_commit() {
    asm volatile("cp.async.commit_group;");
}
template <int N>
__device__ __forceinline__ void cp_wait() {
    asm volatile("cp.async.wait_group %0;" :: "n"(N));
}

// ---------------- kernel 0: zero + dtype detect + W pre-convert ----------------
__global__ void k_init(const unsigned* __restrict__ n2g_words,
                       const float* __restrict__ W1, const float* __restrict__ W2) {
    if (blockIdx.x == 0) {
        __shared__ int nz;
        if (threadIdx.x == 0) nz = 0;
        __syncthreads();
        unsigned acc = 0;
        #pragma unroll
        for (int q = 0; q < 4; ++q)
            acc |= n2g_words[2 * (threadIdx.x * 4 + q) + 1];   // idx <= 2047
        if (acc != 0u) atomicOr(&nz, 1);
        __syncthreads();
        if (threadIdx.x == 0) g_is64 = (nz == 0) ? 1 : 0;
    }
    size_t i = (size_t)blockIdx.x * blockDim.x + threadIdx.x;
    size_t stride = (size_t)gridDim.x * blockDim.x;

    for (size_t k = i; k < 256 * NODE_DIM; k += stride) {
        int r = (int)(k >> 7), c = (int)(k & 127);
        const float* src = (r & 1) ? W2 : W1;
        g_Wtf[k] = f2tf(src[(r >> 1) * NODE_DIM + c]);
    }

    float4* z = reinterpret_cast<float4*>(g_Z1);
    const size_t n4 = (size_t)N_GRAPHS * HIDDEN / 4;
    for (size_t k = i; k < n4; k += stride) z[k] = make_float4(0.f, 0.f, 0.f, 0.f);
    for (size_t k = i; k < N_GRAPHS; k += stride) g_cnti[k] = 0;
}

// ---------------- kernel 1: histogram ----------------
__global__ void k_hist(const void* __restrict__ n2g) {
    int i = blockIdx.x * blockDim.x + threadIdx.x;
    if (i < V_NODES) {
        int g = g_is64 ? (int)reinterpret_cast<const long long*>(n2g)[i]
                       : reinterpret_cast<const int*>(n2g)[i];
        atomicAdd(&g_cnti[g], 1);
    }
}

// ---------------- kernel 2: exclusive scan of counts -> g_pos ----------------
__global__ void k_scan() {   // single block, 1024 threads
    __shared__ int warp_sums[32];
    __shared__ int carry;
    const int tid = threadIdx.x;
    const int lane = tid & 31, w = tid >> 5;
    if (tid == 0) carry = 0;
    __syncthreads();
    for (int base = 0; base < N_GRAPHS; base += 1024) {
        int i = base + tid;
        int v = (i < N_GRAPHS) ? g_cnti[i] : 0;
        int s = v;
        #pragma unroll
        for (int d = 1; d < 32; d <<= 1) {
            int t = __shfl_up_sync(~0u, s, d);
            if (lane >= d) s += t;
        }
        if (lane == 31) warp_sums[w] = s;
        __syncthreads();
        if (w == 0) {
            int t2 = warp_sums[lane];
            #pragma unroll
            for (int d = 1; d < 32; d <<= 1) {
                int t = __shfl_up_sync(~0u, t2, d);
                if (lane >= d) t2 += t;
            }
            warp_sums[lane] = t2;
        }
        __syncthreads();
        int excl = s - v + (w > 0 ? warp_sums[w - 1] : 0) + carry;
        if (i < N_GRAPHS) g_pos[i] = excl;
        __syncthreads();
        if (tid == 1023) carry = excl + v;
        __syncthreads();
    }
}

// ---------------- kernel 3: scatter node ids into graph-grouped order ----------------
__global__ void k_scatter(const void* __restrict__ n2g) {
    int i = blockIdx.x * blockDim.x + threadIdx.x;
    if (i < V_NODES) {
        int g = g_is64 ? (int)reinterpret_cast<const long long*>(n2g)[i]
                       : reinterpret_cast<const int*>(n2g)[i];
        int p = atomicAdd(&g_pos[g], 1);
        g_sorted[p] = i;
        g_sgid[p] = g;
    }
}

// ---------------- kernel 4: node MLP (gated) + segmented reduce ----------------
// 128 sorted nodes/block; tile spans ~7 contiguous graph segments. GEMM as before
// (resident tf32 W, X-only 3-stage cp.async). Epilogue: per-segment smem reduce,
// one red4 per segment per float4 column (atomic lanes cut ~18x).
#define WT_FL   (256 * 132)
#define XSTG_FL (128 * 36)
#define HS_FL   (128 * 132)
#define SMEM_NODES_FL (WT_FL + HS_FL + 128 + 128 + 128 + 128 + 136)
#define SMEM_NODES_BYTES (SMEM_NODES_FL * 4)

__global__ __launch_bounds__(512, 1)
void k_nodes(const float* __restrict__ x,
             const float* __restrict__ b1, const float* __restrict__ b2) {
    extern __shared__ float smem[];
    float* WT  = smem;                    // [256*132] tf32 bits
    float* XS  = smem + WT_FL;            // [3][128*36] (inside HS region)
    float* HS  = smem + WT_FL;            // [128*132] after pipeline drains
    float* B1S = smem + WT_FL + HS_FL;
    float* B2S = B1S + 128;
    int*   SIDX = reinterpret_cast<int*>(B2S + 128);   // sorted node ids
    int*   SGID = SIDX + 128;                          // sorted graph ids
    int*   SEG  = SGID + 128;                          // seg_start[129], [130]=nseg

    const int tid = threadIdx.x;
    const int lane = tid & 31;
    const int wid = tid >> 5;
    const int wm = wid >> 2;
    const int wn = wid & 3;
    const int node0 = blockIdx.x * 128;

    // group 0: resident W copy
    #pragma unroll
    for (int p = 0; p < 16; ++p) {
        int idx = p * 512 + tid;
        int r = idx >> 5, c4 = idx & 31;
        cp16(s2u(WT + r * 132 + c4 * 4), g_Wtf + r * 128 + c4 * 4, 16u);
    }
    cp_commit();

    // sorted ids for this tile (needed before X staging)
    if (tid < 128) {
        int p = node0 + tid;
        if (p < V_NODES) { SIDX[tid] = g_sorted[p]; SGID[tid] = g_sgid[p]; }
        else             { SIDX[tid] = 0;           SGID[tid] = -1; }
    }
    __syncthreads();

    auto issueX = [&](int kc, int buf) {
        float* XSb = XS + buf * XSTG_FL;
        #pragma unroll
        for (int p = 0; p < 2; ++p) {
            int idx = p * 512 + tid;
            int r = idx >> 3, c4 = idx & 7;
            unsigned sz = (node0 + r < V_NODES) ? 16u : 0u;
            int node = SIDX[r];
            cp16(s2u(XSb + r * 36 + c4 * 4),
                 x + (size_t)node * NODE_DIM + kc * 32 + c4 * 4, sz);
        }
        cp_commit();
    };

    issueX(0, 0);
    issueX(1, 1);

    // bias + segment boundaries while copies fly
    if (tid < 128)       B1S[tid]       = b1[tid];
    else if (tid < 256)  B2S[tid - 128] = b2[tid - 128];
    if (tid == 0) {
        int ns = 0, prev = -2;
        for (int r = 0; r < 128; ++r) {
            int g = SGID[r];
            if (g != prev) { SEG[ns++] = r; prev = g; }
        }
        SEG[ns] = 128;
        SEG[130] = ns;
    }

    float c[2][8][4];
    #pragma unroll
    for (int mi = 0; mi < 2; ++mi)
        #pragma unroll
        for (int ni = 0; ni < 8; ++ni)
            #pragma unroll
            for (int q = 0; q < 4; ++q) c[mi][ni][q] = 0.f;

    const int ro = lane >> 2;
    const int col0 = lane & 3;
    const unsigned* WTu = reinterpret_cast<const unsigned*>(WT);

    #pragma unroll
    for (int kc = 0; kc < 4; ++kc) {
        if (kc < 3) cp_wait<1>(); else cp_wait<0>();
        __syncthreads();

        const float* XSf = XS + (kc % 3) * XSTG_FL;
        #pragma unroll
        for (int ks = 0; ks < 4; ++ks) {
            const int co = ks * 8 + col0;
            unsigned a[2][4];
            #pragma unroll
            for (int mi = 0; mi < 2; ++mi) {
                int rb = wm * 32 + mi * 16;
                a[mi][0] = f2tf(XSf[(rb + ro) * 36 + co]);
                a[mi][1] = f2tf(XSf[(rb + ro + 8) * 36 + co]);
                a[mi][2] = f2tf(XSf[(rb + ro) * 36 + co + 4]);
                a[mi][3] = f2tf(XSf[(rb + ro + 8) * 36 + co + 4]);
            }
            const int wco = kc * 32 + ks * 8 + col0;
            #pragma unroll
            for (int ni = 0; ni < 8; ++ni) {
                int nr = wn * 64 + ni * 8 + ro;
                unsigned bb0 = WTu[nr * 132 + wco];
                unsigned bb1 = WTu[nr * 132 + wco + 4];
                mma_tf32(c[0][ni][0], c[0][ni][1], c[0][ni][2], c[0][ni][3],
                         a[0][0], a[0][1], a[0][2], a[0][3], bb0, bb1);
                mma_tf32(c[1][ni][0], c[1][ni][1], c[1][ni][2], c[1][ni][3],
                         a[1][0], a[1][1], a[1][2], a[1][3], bb0, bb1);
            }
        }

        if (kc + 2 <= 3) issueX(kc + 2, (kc + 2) % 3);
    }

    __syncthreads();   // X staging dead; HS aliases it

    // epilogue: gate -> HS (C col pairs: even=lin1[j], odd=lin2[j])
    #pragma unroll
    for (int ni = 0; ni < 8; ++ni) {
        int j = wn * 32 + ni * 4 + col0;
        float bb1 = B1S[j], bb2 = B2S[j];
        int r = wm * 32 + ro;
        HS[r * 132 + j]        = (c[0][ni][0] + bb1) * sigm(c[0][ni][1] + bb2);
        HS[(r + 8) * 132 + j]  = (c[0][ni][2] + bb1) * sigm(c[0][ni][3] + bb2);
        HS[(r + 16) * 132 + j] = (c[1][ni][0] + bb1) * sigm(c[1][ni][1] + bb2);
        HS[(r + 24) * 132 + j] = (c[1][ni][2] + bb1) * sigm(c[1][ni][3] + bb2);
    }
    __syncthreads();

    // segmented reduce: thread (s = tid/32 stride 16, c4 = tid&31)
    const int nseg = SEG[130];
    const int c4 = tid & 31;
    for (int s = tid >> 5; s < nseg; s += 16) {
        int r0 = SEG[s], r1 = SEG[s + 1];
        int g = SGID[r0];
        if (g < 0) continue;
        float4 acc = make_float4(0.f, 0.f, 0.f, 0.f);
        for (int r = r0; r < r1; ++r) {
            float4 v = *reinterpret_cast<const float4*>(HS + r * 132 + c4 * 4);
            acc.x += v.x; acc.y += v.y; acc.z += v.z; acc.w += v.w;
        }
        red4(&g_Z1[(size_t)g * HIDDEN + c4 * 4], acc);
    }
}

// ---------------- kernel 5: readout GEMM ----------------
#define G_STAGE_FL (128*36 + 128*36)
#define SMEM_GRAPHS_FL (3*G_STAGE_FL + 128 + 128)
#define SMEM_GRAPHS_BYTES (SMEM_GRAPHS_FL * 4)

__global__ __launch_bounds__(256, 2)
void k_graphs(const float* __restrict__ gx, const float* __restrict__ W3,
              const float* __restrict__ b3, float* __restrict__ out) {
    extern __shared__ float smem[];
    float* SS  = smem + 3 * G_STAGE_FL;
    float* B3S = SS + 128;

    const int tid = threadIdx.x;
    const int lane = tid & 31;
    const int wid = tid >> 5;
    const int wm = wid >> 2;
    const int wn = wid & 3;
    const int g0 = blockIdx.x * 128;

    auto issue = [&](int kc, int buf) {
        float* ZSb = smem + buf * G_STAGE_FL;
        float* WSb = ZSb + 128 * 36;
        #pragma unroll
        for (int p = 0; p < 4; ++p) {
            int idx = p * 256 + tid;
            int r = idx >> 3, c4 = idx & 7;
            int g = g0 + r;
            unsigned sz = (g < N_GRAPHS) ? 16u : 0u;
            int gc = (g < N_GRAPHS) ? g : (N_GRAPHS - 1);
            const float* src;
            if (kc < 4)      src = g_Z1 + (size_t)gc * HIDDEN + kc * 32 + c4 * 4;
            else if (kc < 8) src = g_Z1 + (size_t)gc * HIDDEN + (kc - 4) * 32 + c4 * 4;
            else             src = gx + (size_t)gc * GDIM + (kc - 8) * 32 + c4 * 4;
            cp16(s2u(ZSb + r * 36 + c4 * 4), src, sz);
        }
        #pragma unroll
        for (int p = 0; p < 4; ++p) {
            int idx = p * 256 + tid;
            int j = idx >> 3, c4 = idx & 7;
            cp16(s2u(WSb + j * 36 + c4 * 4),
                 W3 + (size_t)j * 320 + kc * 32 + c4 * 4, 16u);
        }
        cp_commit();
    };

    issue(0, 0);
    issue(1, 1);

    if (tid < 128) {
        int g = g0 + tid;
        float cn = (g < N_GRAPHS) ? (float)g_cnti[g] : 1.0f;
        SS[tid] = 1.0f / fmaxf(cn, 1.0f);
        B3S[tid] = b3[tid];
    }

    float c[4][4][4];
    #pragma unroll
    for (int mi = 0; mi < 4; ++mi)
        #pragma unroll
        for (int ni = 0; ni < 4; ++ni)
            #pragma unroll
            for (int q = 0; q < 4; ++q) c[mi][ni][q] = 0.f;

    const int ro = lane >> 2;
    const int col0 = lane & 3;

    for (int kc = 0; kc < 10; ++kc) {
        if (kc < 9) cp_wait<1>(); else cp_wait<0>();
        __syncthreads();

        const float* ZSf = smem + (kc % 3) * G_STAGE_FL;
        const float* WSf = ZSf + 128 * 36;
        const bool isZ2 = (kc >= 4) && (kc < 8);

        float s0[4], s1[4];
        #pragma unroll
        for (int mi = 0; mi < 4; ++mi) {
            int rb = wm * 64 + mi * 16;
            s0[mi] = isZ2 ? SS[rb + ro]     : 1.0f;
            s1[mi] = isZ2 ? SS[rb + ro + 8] : 1.0f;
        }

        #pragma unroll
        for (int ks = 0; ks < 4; ++ks) {
            const int co = ks * 8 + col0;
            unsigned a[4][4];
            #pragma unroll
            for (int mi = 0; mi < 4; ++mi) {
                int rb = wm * 64 + mi * 16;
                a[mi][0] = f2tf(ZSf[(rb + ro) * 36 + co]     * s0[mi]);
                a[mi][1] = f2tf(ZSf[(rb + ro + 8) * 36 + co] * s1[mi]);
                a[mi][2] = f2tf(ZSf[(rb + ro) * 36 + co + 4]     * s0[mi]);
                a[mi][3] = f2tf(ZSf[(rb + ro + 8) * 36 + co + 4] * s1[mi]);
            }
            #pragma unroll
            for (int ni = 0; ni < 4; ++ni) {
                int nr = wn * 32 + ni * 8 + ro;
                unsigned bb0 = f2tf(WSf[nr * 36 + co]);
                unsigned bb1 = f2tf(WSf[nr * 36 + co + 4]);
                #pragma unroll
                for (int mi = 0; mi < 4; ++mi)
                    mma_tf32(c[mi][ni][0], c[mi][ni][1], c[mi][ni][2], c[mi][ni][3],
                             a[mi][0], a[mi][1], a[mi][2], a[mi][3], bb0, bb1);
            }
        }

        if (kc + 2 <= 9) issue(kc + 2, (kc + 2) % 3);
    }

    #pragma unroll
    for (int mi = 0; mi < 4; ++mi) {
        #pragma unroll
        for (int ni = 0; ni < 4; ++ni) {
            int r = wm * 64 + mi * 16 + ro;
            int n = wn * 32 + ni * 8 + 2 * col0;
            int g = g0 + r;
            if (g < N_GRAPHS) {
                float2 v;
                v.x = fmaxf(c[mi][ni][0] + B3S[n], 0.f);
                v.y = fmaxf(c[mi][ni][1] + B3S[n + 1], 0.f);
                *reinterpret_cast<float2*>(out + (size_t)g * 128 + n) = v;
            }
            int g2 = g0 + r + 8;
            if (g2 < N_GRAPHS) {
                float2 v;
                v.x = fmaxf(c[mi][ni][2] + B3S[n], 0.f);
                v.y = fmaxf(c[mi][ni][3] + B3S[n + 1], 0.f);
                *reinterpret_cast<float2*>(out + (size_t)g2 * 128 + n) = v;
            }
        }
    }
}

// ---------------- launch ----------------
extern "C" void kernel_launch(void* const* d_in, const int* in_sizes, int n_in,
                              void* d_out, int out_size) {
    const float* x  = (const float*)d_in[0];
    const void*  n2g = d_in[1];
    const float* gx = (const float*)d_in[2];
    const float* W1 = (const float*)d_in[3];
    const float* b1 = (const float*)d_in[4];
    const float* W2 = (const float*)d_in[5];
    const float* b2 = (const float*)d_in[6];
    const float* W3 = (const float*)d_in[7];
    const float* b3 = (const float*)d_in[8];
    float* out = (float*)d_out;

    static bool attr_set = false;
    if (!attr_set) {
        cudaFuncSetAttribute(k_nodes, cudaFuncAttributeMaxDynamicSharedMemorySize,
                             SMEM_NODES_BYTES);
        cudaFuncSetAttribute(k_graphs, cudaFuncAttributeMaxDynamicSharedMemorySize,
                             SMEM_GRAPHS_BYTES);
        attr_set = true;
    }

    k_init<<<2048, 256>>>((const unsigned*)n2g, W1, W2);
    k_hist<<<(V_NODES + 255) / 256, 256>>>(n2g);
    k_scan<<<1, 1024>>>();
    k_scatter<<<(V_NODES + 255) / 256, 256>>>(n2g);
    k_nodes<<<(V_NODES + 127) / 128, 512, SMEM_NODES_BYTES>>>(x, b1, b2);
    k_graphs<<<(N_GRAPHS + 127) / 128, 256, SMEM_GRAPHS_BYTES>>>(gx, W3, b3, out);
}